// round 13
// baseline (speedup 1.0000x reference)
#include <cuda_runtime.h>
#include <cuda_fp16.h>
#include <cstdint>
#include <math.h>

// Problem constants
#define Bz   4
#define S1z  1024
#define S2z  1024
#define Dz   1024
#define Hz   16
#define DKz  64
#define FFNz 4096

#define MROWS (Bz * S1z)        // 4096
#define HROWS (MROWS / 2)       // 2048 rows per half (2 batches)

// ---------------- scratch ----------------
__device__ float  g_y   [Bz * S1z * Dz];
__device__ float  g_x2  [Bz * S1z * Dz];
__device__ __half g_y16  [Bz * S1z * Dz];
__device__ __half g_kvn16[Bz * S2z * Dz];
__device__ __half g_q16  [Bz * S1z * Dz];
__device__ __half g_kv16 [(size_t)Bz * S2z * 4096];  // k0|v0|k1|v1, ld=4096
__device__ __half g_o16  [Bz * S1z * Dz];
__device__ __half g_yf16 [Bz * S1z * Dz];
__device__ __half g_h16  [(size_t)Bz * S1z * FFNz];
__device__ __half g_wth  [16 * 1024 * 1024];

// ---------------- helpers ----------------
__device__ __forceinline__ uint32_t smem_u32(const void* p) {
    return (uint32_t)__cvta_generic_to_shared(p);
}
__device__ __forceinline__ void cp16(uint32_t dst, const void* src) {
    asm volatile("cp.async.cg.shared.global [%0], [%1], 16;" :: "r"(dst), "l"(src));
}
__device__ __forceinline__ void mma_f16(float* c, const uint32_t* a, const uint32_t* b) {
    asm volatile("mma.sync.aligned.m16n8k16.row.col.f32.f16.f16.f32 "
                 "{%0,%1,%2,%3},{%4,%5,%6,%7},{%8,%9},{%0,%1,%2,%3};"
                 : "+f"(c[0]), "+f"(c[1]), "+f"(c[2]), "+f"(c[3])
                 : "r"(a[0]), "r"(a[1]), "r"(a[2]), "r"(a[3]), "r"(b[0]), "r"(b[1]));
}
__device__ __forceinline__ void ldsm4(uint32_t* r, uint32_t addr) {
    asm volatile("ldmatrix.sync.aligned.m8n8.x4.shared.b16 {%0,%1,%2,%3}, [%4];"
                 : "=r"(r[0]), "=r"(r[1]), "=r"(r[2]), "=r"(r[3]) : "r"(addr));
}
__device__ __forceinline__ void ldsm4t(uint32_t* r, uint32_t addr) {
    asm volatile("ldmatrix.sync.aligned.m8n8.x4.trans.shared.b16 {%0,%1,%2,%3}, [%4];"
                 : "=r"(r[0]), "=r"(r[1]), "=r"(r[2]), "=r"(r[3]) : "r"(addr));
}
__device__ __forceinline__ uint32_t h2pack(float a, float b) {
    __half2 h = __floats2half2_rn(a, b);
    return *(uint32_t*)&h;
}

// ---------------- fp16 tensor-core GEMM (at mma.sync ceiling — unchanged) ----
#define HSTR 40
#define HSTAGE (256 * HSTR * 2)
#define GEMM_SMEM (3 * HSTAGE)

__global__ void __launch_bounds__(256)
hgemm(int K,
      const __half* __restrict__ A, int lda,
      const __half* __restrict__ Bt, int ldb,
      float* __restrict__ C32, __half* __restrict__ C16, int ldc,
      const float* __restrict__ bias,
      const float* __restrict__ res, int ldres, int relu)
{
    extern __shared__ __align__(16) char smc[];
    int tid = threadIdx.x;
    int bm = blockIdx.y * 128, bn = blockIdx.x * 128;
    int warp = tid >> 5, lane = tid & 31, g = lane >> 2, tg = lane & 3;
    int wn = warp & 1, wm = warp >> 1;

    uint32_t sb = smem_u32(smc);
    const int NT = K / 32;

    auto issue = [&](int t) {
        uint32_t base = sb + (uint32_t)((t % 3) * HSTAGE);
        #pragma unroll
        for (int i = 0; i < 2; i++) {
            int e = tid + i * 256, r = e >> 2, c = (e & 3) * 8;
            cp16(base + (uint32_t)(r * HSTR + c) * 2u,
                 A + (size_t)(bm + r) * lda + t * 32 + c);
        }
        #pragma unroll
        for (int i = 0; i < 2; i++) {
            int e = tid + i * 256, r = e >> 2, c = (e & 3) * 8;
            cp16(base + (uint32_t)((128 + r) * HSTR + c) * 2u,
                 Bt + (size_t)(bn + r) * ldb + t * 32 + c);
        }
        asm volatile("cp.async.commit_group;");
    };

    int q = lane >> 3, rr = lane & 7;
    uint32_t a_off[2][2];
    #pragma unroll
    for (int mi = 0; mi < 2; mi++)
        #pragma unroll
        for (int ks = 0; ks < 2; ks++)
            a_off[mi][ks] = (uint32_t)(((wm*32 + mi*16 + (q&1)*8 + rr) * HSTR
                                        + ks*16 + (q>>1)*8) * 2);
    uint32_t b_off[4][2];
    #pragma unroll
    for (int jp = 0; jp < 4; jp++)
        #pragma unroll
        for (int ks = 0; ks < 2; ks++)
            b_off[jp][ks] = (uint32_t)(((128 + wn*64 + jp*16 + (q>>1)*8 + rr) * HSTR
                                        + ks*16 + (q&1)*8) * 2);

    float acc[2][8][4] = {};

    issue(0);
    if (NT > 1) issue(1);

    for (int t = 0; t < NT; t++) {
        if (t + 1 < NT) asm volatile("cp.async.wait_group 1;");
        else            asm volatile("cp.async.wait_group 0;");
        __syncthreads();
        if (t + 2 < NT) issue(t + 2);

        uint32_t stage = sb + (uint32_t)((t % 3) * HSTAGE);
        #pragma unroll
        for (int ks = 0; ks < 2; ks++) {
            uint32_t a[2][4], b[4][4];
            #pragma unroll
            for (int mi = 0; mi < 2; mi++) ldsm4(a[mi], stage + a_off[mi][ks]);
            #pragma unroll
            for (int jp = 0; jp < 4; jp++) ldsm4(b[jp], stage + b_off[jp][ks]);
            #pragma unroll
            for (int mi = 0; mi < 2; mi++)
                #pragma unroll
                for (int jp = 0; jp < 4; jp++) {
                    mma_f16(acc[mi][jp*2],     a[mi], &b[jp][0]);
                    mma_f16(acc[mi][jp*2 + 1], a[mi], &b[jp][2]);
                }
        }
    }

    #pragma unroll
    for (int mi = 0; mi < 2; mi++) {
        #pragma unroll
        for (int j = 0; j < 8; j++) {
            int m0 = bm + wm*32 + mi*16 + g;
            int n0 = bn + wn*64 + j*8 + 2*tg;
            float v0 = acc[mi][j][0], v1 = acc[mi][j][1];
            float v2 = acc[mi][j][2], v3 = acc[mi][j][3];
            if (bias) {
                float b0 = bias[n0], b1 = bias[n0 + 1];
                v0 += b0; v1 += b1; v2 += b0; v3 += b1;
            }
            if (res) {
                v0 += res[(size_t)m0*ldres + n0];
                v1 += res[(size_t)m0*ldres + n0 + 1];
                v2 += res[(size_t)(m0 + 8)*ldres + n0];
                v3 += res[(size_t)(m0 + 8)*ldres + n0 + 1];
            }
            if (relu) {
                v0 = fmaxf(v0, 0.f); v1 = fmaxf(v1, 0.f);
                v2 = fmaxf(v2, 0.f); v3 = fmaxf(v3, 0.f);
            }
            if (C32) {
                *(float2*)&C32[(size_t)m0*ldc + n0]       = make_float2(v0, v1);
                *(float2*)&C32[(size_t)(m0 + 8)*ldc + n0] = make_float2(v2, v3);
            }
            if (C16) {
                *(__half2*)&C16[(size_t)m0*ldc + n0]       = __floats2half2_rn(v0, v1);
                *(__half2*)&C16[(size_t)(m0 + 8)*ldc + n0] = __floats2half2_rn(v2, v3);
            }
        }
    }
}

// ---------------- transpose + fp32->fp16 -------------------------------------
__global__ void transpose8_kernel(
    const float* s0, __half* d0, const float* s1, __half* d1,
    const float* s2, __half* d2, const float* s3, __half* d3,
    const float* s4, __half* d4, const float* s5, __half* d5,
    const float* s6, __half* d6, const float* s7, __half* d7)
{
    __shared__ float tile[32][33];
    const float* src; __half* dst;
    switch (blockIdx.z) {
        case 0: src = s0; dst = d0; break;
        case 1: src = s1; dst = d1; break;
        case 2: src = s2; dst = d2; break;
        case 3: src = s3; dst = d3; break;
        case 4: src = s4; dst = d4; break;
        case 5: src = s5; dst = d5; break;
        case 6: src = s6; dst = d6; break;
        default: src = s7; dst = d7; break;
    }
    int tx = threadIdx.x, ty = threadIdx.y;
    int c0 = blockIdx.x * 32, r0 = blockIdx.y * 32;
    #pragma unroll
    for (int j = 0; j < 32; j += 8)
        tile[ty + j][tx] = src[(size_t)(r0 + ty + j) * Dz + c0 + tx];
    __syncthreads();
    #pragma unroll
    for (int j = 0; j < 32; j += 8)
        dst[(size_t)(c0 + ty + j) * Dz + r0 + tx] = __float2half_rn(tile[tx][ty + j]);
}

__global__ void transpose_kernel(const float* __restrict__ src, __half* __restrict__ dst,
                                 int R, int C)
{
    __shared__ float tile[32][33];
    int tx = threadIdx.x, ty = threadIdx.y;
    int c0 = blockIdx.x * 32, r0 = blockIdx.y * 32;
    #pragma unroll
    for (int j = 0; j < 32; j += 8)
        tile[ty + j][tx] = src[(size_t)(r0 + ty + j) * C + c0 + tx];
    __syncthreads();
    #pragma unroll
    for (int j = 0; j < 32; j += 8)
        dst[(size_t)(c0 + ty + j) * R + r0 + tx] = __float2half_rn(tile[tx][ty + j]);
}

// ---------------- LayerNorm core ----------------------------------------------
__device__ __forceinline__ void ln_row(float4 v,
                                       float* out32, __half* out16, size_t row, int tid,
                                       const float* __restrict__ g,
                                       const float* __restrict__ bta)
{
    float s = v.x + v.y + v.z + v.w;
    float q = v.x*v.x + v.y*v.y + v.z*v.z + v.w*v.w;
    #pragma unroll
    for (int o = 16; o; o >>= 1) {
        s += __shfl_xor_sync(0xffffffffu, s, o);
        q += __shfl_xor_sync(0xffffffffu, q, o);
    }
    __shared__ float ss[8], qq[8];
    int lane = tid & 31, wid = tid >> 5;
    if (!lane) { ss[wid] = s; qq[wid] = q; }
    __syncthreads();
    if (tid < 32) {
        s = (tid < 8) ? ss[tid] : 0.f;
        q = (tid < 8) ? qq[tid] : 0.f;
        #pragma unroll
        for (int o = 4; o; o >>= 1) {
            s += __shfl_xor_sync(0xffffffffu, s, o);
            q += __shfl_xor_sync(0xffffffffu, q, o);
        }
        if (!tid) { ss[0] = s; qq[0] = q; }
    }
    __syncthreads();
    float mean = ss[0] * (1.f / Dz);
    float var  = qq[0] * (1.f / Dz) - mean * mean;
    float inv  = rsqrtf(var + 1e-5f);
    float4 gv = ((const float4*)g)[tid];
    float4 bv = ((const float4*)bta)[tid];
    float4 o4;
    o4.x = (v.x - mean) * inv * gv.x + bv.x;
    o4.y = (v.y - mean) * inv * gv.y + bv.y;
    o4.z = (v.z - mean) * inv * gv.z + bv.z;
    o4.w = (v.w - mean) * inv * gv.w + bv.w;
    if (out32) ((float4*)(out32 + row * (size_t)Dz))[tid] = o4;
    if (out16) {
        __half2 h0 = __floats2half2_rn(o4.x, o4.y);
        __half2 h1 = __floats2half2_rn(o4.z, o4.w);
        uint2 u = make_uint2(*(uint32_t*)&h0, *(uint32_t*)&h1);
        ((uint2*)(out16 + row * (size_t)Dz))[tid] = u;
    }
}

// LN over n1 rows of x (-> y32,y16) and rows of kv (-> kvn16); pointers pre-offset
__global__ void ln_dual_kernel(const float* __restrict__ x, const float* __restrict__ kv,
                               float* __restrict__ y32, __half* __restrict__ y16,
                               __half* __restrict__ kvn16, int n1,
                               const float* __restrict__ g, const float* __restrict__ bta)
{
    int tid = threadIdx.x;
    if ((int)blockIdx.x < n1) {
        size_t row = blockIdx.x;
        float4 v = ((const float4*)(x + row * (size_t)Dz))[tid];
        ln_row(v, y32, y16, row, tid, g, bta);
    } else {
        size_t row = blockIdx.x - n1;
        float4 v = ((const float4*)(kv + row * (size_t)Dz))[tid];
        ln_row(v, nullptr, kvn16, row, tid, g, bta);
    }
}

__global__ void ln_add_kernel(const float* __restrict__ in, const float* __restrict__ add,
                              float* __restrict__ sum32, __half* __restrict__ out16,
                              const float* __restrict__ g, const float* __restrict__ bta)
{
    size_t row = blockIdx.x;
    int tid = threadIdx.x;
    float4 v = ((const float4*)(in + row * (size_t)Dz))[tid];
    float4 a4 = ((const float4*)(add + row * (size_t)Dz))[tid];
    v.x += a4.x; v.y += a4.y; v.z += a4.z; v.w += a4.w;
    ((float4*)(sum32 + row * (size_t)Dz))[tid] = v;
    ln_row(v, nullptr, out16, row, tid, g, bta);
}

// ---------------- fused fp16 flash cross-attention (exp2 softmax) ------------
#define FSTR 72
#define FLASH_SMEM ((2*64*FSTR + 2*64*FSTR) * 2 + S2z * 4)
#define SCALE2 0.180336880f   // 0.125 * log2(e)

__global__ void __launch_bounds__(256)
flash16_kernel(const __half* __restrict__ Q, const __half* __restrict__ Kg,
               const __half* __restrict__ Vg, int ldkv,
               const int* __restrict__ mask, __half* __restrict__ O16)
{
    extern __shared__ char smc[];
    __half* Ks = (__half*)smc;
    __half* Vs = Ks + 2*64*FSTR;
    float*  Mf = (float*)(Vs + 2*64*FSTR);

    int bh = blockIdx.y;
    int b = bh / Hz, h = bh % Hz;     // b local to pre-offset pointers
    int q0 = blockIdx.x * 128;
    int tid = threadIdx.x, warp = tid >> 5, lane = tid & 31, g = lane >> 2, tg = lane & 3;
    int q2 = lane >> 3, rr = lane & 7;

    const __half* Qb = Q  + ((size_t)(b*S1z + q0))*Dz + h*DKz;
    const __half* Kb = Kg + (size_t)b*S2z*ldkv + h*DKz;
    const __half* Vb = Vg + (size_t)b*S2z*ldkv + h*DKz;

    for (int i = tid; i < S2z; i += 256) Mf[i] = mask[(size_t)b*S2z + i] ? 1.f : 0.f;

    uint32_t qa[4][4];
    {
        int ml = warp*16 + g, mh = ml + 8;
        #pragma unroll
        for (int ki = 0; ki < 4; ki++) {
            qa[ki][0] = *(const uint32_t*)&Qb[(size_t)ml*Dz + ki*16 + tg*2];
            qa[ki][1] = *(const uint32_t*)&Qb[(size_t)mh*Dz + ki*16 + tg*2];
            qa[ki][2] = *(const uint32_t*)&Qb[(size_t)ml*Dz + ki*16 + 8 + tg*2];
            qa[ki][3] = *(const uint32_t*)&Qb[(size_t)mh*Dz + ki*16 + 8 + tg*2];
        }
    }

    uint32_t ksb = smem_u32(Ks), vsb = smem_u32(Vs);

    auto issue = [&](int t) {
        int buf = t & 1;
        #pragma unroll
        for (int i = 0; i < 2; i++) {
            int e = tid + i*256, r = e >> 3, c = (e & 7) * 8;
            cp16(ksb + (uint32_t)(buf*64*FSTR + r*FSTR + c)*2u,
                 Kb + (size_t)(t*64 + r)*ldkv + c);
        }
        #pragma unroll
        for (int i = 0; i < 2; i++) {
            int e = tid + i*256, r = e >> 3, c = (e & 7) * 8;
            cp16(vsb + (uint32_t)(buf*64*FSTR + r*FSTR + c)*2u,
                 Vb + (size_t)(t*64 + r)*ldkv + c);
        }
        asm volatile("cp.async.commit_group;");
    };

    uint32_t kb_off[4][4];
    #pragma unroll
    for (int jp = 0; jp < 4; jp++)
        #pragma unroll
        for (int ki = 0; ki < 4; ki++)
            kb_off[jp][ki] = (uint32_t)(((jp*16 + (q2>>1)*8 + rr) * FSTR
                                         + ki*16 + (q2&1)*8) * 2);
    uint32_t vb_off[4][4];
    #pragma unroll
    for (int ki = 0; ki < 4; ki++)
        #pragma unroll
        for (int jp = 0; jp < 4; jp++)
            vb_off[ki][jp] = (uint32_t)(((ki*16 + (q2&1)*8 + rr) * FSTR
                                         + jp*16 + (q2>>1)*8) * 2);

    float s_acc[8][4];
    float o_acc[8][4] = {};
    float m_lo = -INFINITY, m_hi = -INFINITY, l_lo = 0.f, l_hi = 0.f;
    int rl = warp*16 + g, rh = rl + 8;

    issue(0);
    for (int t = 0; t < S2z/64; t++) {
        if (t + 1 < S2z/64) { issue(t + 1); asm volatile("cp.async.wait_group 1;"); }
        else                { asm volatile("cp.async.wait_group 0;"); }
        __syncthreads();
        int buf = t & 1;
        uint32_t kbase = ksb + (uint32_t)(buf*64*FSTR)*2u;
        uint32_t vbase = vsb + (uint32_t)(buf*64*FSTR)*2u;

        #pragma unroll
        for (int j = 0; j < 8; j++)
            s_acc[j][0] = s_acc[j][1] = s_acc[j][2] = s_acc[j][3] = 0.f;
        #pragma unroll
        for (int ki = 0; ki < 4; ki++) {
            uint32_t bf[4][4];
            #pragma unroll
            for (int jp = 0; jp < 4; jp++) ldsm4(bf[jp], kbase + kb_off[jp][ki]);
            #pragma unroll
            for (int jp = 0; jp < 4; jp++) {
                mma_f16(s_acc[jp*2],     qa[ki], &bf[jp][0]);
                mma_f16(s_acc[jp*2 + 1], qa[ki], &bf[jp][2]);
            }
        }

        float rmax_lo = -INFINITY, rmax_hi = -INFINITY;
        #pragma unroll
        for (int j = 0; j < 8; j++) {
            int c0 = t*64 + j*8 + 2*tg;
            float mf0 = Mf[c0], mf1 = Mf[c0 + 1];
            s_acc[j][0] = (mf0 != 0.f) ? s_acc[j][0]*SCALE2 : -1e9f;
            s_acc[j][1] = (mf1 != 0.f) ? s_acc[j][1]*SCALE2 : -1e9f;
            s_acc[j][2] = (mf0 != 0.f) ? s_acc[j][2]*SCALE2 : -1e9f;
            s_acc[j][3] = (mf1 != 0.f) ? s_acc[j][3]*SCALE2 : -1e9f;
            rmax_lo = fmaxf(rmax_lo, fmaxf(s_acc[j][0], s_acc[j][1]));
            rmax_hi = fmaxf(rmax_hi, fmaxf(s_acc[j][2], s_acc[j][3]));
        }
        rmax_lo = fmaxf(rmax_lo, __shfl_xor_sync(0xffffffffu, rmax_lo, 1));
        rmax_lo = fmaxf(rmax_lo, __shfl_xor_sync(0xffffffffu, rmax_lo, 2));
        rmax_hi = fmaxf(rmax_hi, __shfl_xor_sync(0xffffffffu, rmax_hi, 1));
        rmax_hi = fmaxf(rmax_hi, __shfl_xor_sync(0xffffffffu, rmax_hi, 2));
        float mn_lo = fmaxf(m_lo, rmax_lo), mn_hi = fmaxf(m_hi, rmax_hi);
        float al_lo = exp2f(m_lo - mn_lo), al_hi = exp2f(m_hi - mn_hi);
        m_lo = mn_lo; m_hi = mn_hi;

        float sum_lo = 0.f, sum_hi = 0.f;
        #pragma unroll
        for (int j = 0; j < 8; j++) {
            s_acc[j][0] = exp2f(s_acc[j][0] - mn_lo);
            s_acc[j][1] = exp2f(s_acc[j][1] - mn_lo);
            s_acc[j][2] = exp2f(s_acc[j][2] - mn_hi);
            s_acc[j][3] = exp2f(s_acc[j][3] - mn_hi);
            sum_lo += s_acc[j][0] + s_acc[j][1];
            sum_hi += s_acc[j][2] + s_acc[j][3];
        }
        sum_lo += __shfl_xor_sync(0xffffffffu, sum_lo, 1);
        sum_lo += __shfl_xor_sync(0xffffffffu, sum_lo, 2);
        sum_hi += __shfl_xor_sync(0xffffffffu, sum_hi, 1);
        sum_hi += __shfl_xor_sync(0xffffffffu, sum_hi, 2);
        l_lo = al_lo*l_lo + sum_lo;
        l_hi = al_hi*l_hi + sum_hi;
        #pragma unroll
        for (int j = 0; j < 8; j++) {
            o_acc[j][0] *= al_lo; o_acc[j][1] *= al_lo;
            o_acc[j][2] *= al_hi; o_acc[j][3] *= al_hi;
        }

        #pragma unroll
        for (int ki = 0; ki < 4; ki++) {
            uint32_t pa[4];
            pa[0] = h2pack(s_acc[2*ki    ][0], s_acc[2*ki    ][1]);
            pa[1] = h2pack(s_acc[2*ki    ][2], s_acc[2*ki    ][3]);
            pa[2] = h2pack(s_acc[2*ki + 1][0], s_acc[2*ki + 1][1]);
            pa[3] = h2pack(s_acc[2*ki + 1][2], s_acc[2*ki + 1][3]);
            #pragma unroll
            for (int jp = 0; jp < 4; jp++) {
                uint32_t vb[4];
                ldsm4t(vb, vbase + vb_off[ki][jp]);
                mma_f16(o_acc[jp*2],     pa, &vb[0]);
                mma_f16(o_acc[jp*2 + 1], pa, &vb[2]);
            }
        }
        __syncthreads();
    }

    float il_lo = 1.f / l_lo, il_hi = 1.f / l_hi;
    __half* Ob = O16 + ((size_t)(b*S1z + q0))*Dz + h*DKz;
    #pragma unroll
    for (int j = 0; j < 8; j++) {
        int c = j*8 + 2*tg;
        *(__half2*)&Ob[(size_t)rl*Dz + c] =
            __floats2half2_rn(o_acc[j][0]*il_lo, o_acc[j][1]*il_lo);
        *(__half2*)&Ob[(size_t)rh*Dz + c] =
            __floats2half2_rn(o_acc[j][2]*il_hi, o_acc[j][3]*il_hi);
    }
}

// ---------------- host orchestration ----------------
extern "C" void kernel_launch(void* const* d_in, const int* in_sizes, int n_in,
                              void* d_out, int out_size)
{
    const float* x     = (const float*)d_in[0];
    const float* kv    = (const float*)d_in[1];
    const int*   mask  = (const int*)  d_in[2];
    const float* ln1_g = (const float*)d_in[3];
    const float* ln1_b = (const float*)d_in[4];
    const float* qw[2] = { (const float*)d_in[5],  (const float*)d_in[10] };
    const float* kw[2] = { (const float*)d_in[6],  (const float*)d_in[11] };
    const float* vw[2] = { (const float*)d_in[7],  (const float*)d_in[12] };
    const float* ow[2] = { (const float*)d_in[8],  (const float*)d_in[13] };
    const float* ob[2] = { (const float*)d_in[9],  (const float*)d_in[14] };
    const float* ln2_g = (const float*)d_in[15];
    const float* ln2_b = (const float*)d_in[16];
    const float* w1    = (const float*)d_in[17];
    const float* b1    = (const float*)d_in[18];
    const float* w2    = (const float*)d_in[19];
    const float* b2    = (const float*)d_in[20];
    float* out = (float*)d_out;

    float *y, *x2;
    __half *y16, *kvn16, *q16, *kv16, *o16, *yf16, *h16, *wth;
    cudaGetSymbolAddress((void**)&y,     g_y);
    cudaGetSymbolAddress((void**)&x2,    g_x2);
    cudaGetSymbolAddress((void**)&y16,   g_y16);
    cudaGetSymbolAddress((void**)&kvn16, g_kvn16);
    cudaGetSymbolAddress((void**)&q16,   g_q16);
    cudaGetSymbolAddress((void**)&kv16,  g_kv16);
    cudaGetSymbolAddress((void**)&o16,   g_o16);
    cudaGetSymbolAddress((void**)&yf16,  g_yf16);
    cudaGetSymbolAddress((void**)&h16,   g_h16);
    cudaGetSymbolAddress((void**)&wth,   g_wth);

    cudaFuncSetAttribute(flash16_kernel,
        cudaFuncAttributeMaxDynamicSharedMemorySize, FLASH_SMEM);
    cudaFuncSetAttribute(hgemm,
        cudaFuncAttributeMaxDynamicSharedMemorySize, GEMM_SMEM);

    // one-time side stream + events (same footprint as R11, which passed)
    static cudaStream_t s1 = nullptr;
    static cudaEvent_t evFork = nullptr, evW = nullptr, evLN = nullptr, evEnd = nullptr;
    if (!s1) {
        cudaStreamCreateWithFlags(&s1, cudaStreamNonBlocking);
        cudaEventCreateWithFlags(&evFork, cudaEventDisableTiming);
        cudaEventCreateWithFlags(&evW,    cudaEventDisableTiming);
        cudaEventCreateWithFlags(&evLN,   cudaEventDisableTiming);
        cudaEventCreateWithFlags(&evEnd,  cudaEventDisableTiming);
    }

    const size_t MM = 1024 * 1024;
    __half* qwt[2] = { wth + 0*MM, wth + 1*MM };
    __half* owt[2] = { wth + 2*MM, wth + 3*MM };
    __half* kvwt   = wth + 4*MM;
    __half* w1t    = wth + 8*MM;
    __half* w2t    = wth + 12*MM;

    dim3 tb(32, 8);
    dim3 gProjH(Dz/128, HROWS/128);     // (8, 16)
    dim3 gKVH(4096/128, HROWS/128);     // (32, 16)
    dim3 gFlashH(S1z/128, 2*Hz);        // (8, 32)
    dim3 gF1H(FFNz/128, HROWS/128);     // (32, 16)

    // fork
    cudaEventRecord(evFork, 0);
    cudaStreamWaitEvent(s1, evFork, 0);

    // s1: weight transposes — run concurrent with the full LN on stream 0
    transpose8_kernel<<<dim3(32,32,8), tb, 0, s1>>>(
        qw[0], qwt[0], qw[1], qwt[1], ow[0], owt[0], ow[1], owt[1],
        kw[0], kvwt + 0*MM, vw[0], kvwt + 1*MM, kw[1], kvwt + 2*MM, vw[1], kvwt + 3*MM);
    transpose_kernel<<<dim3(FFNz/32, Dz/32), tb, 0, s1>>>(w1, w1t, Dz, FFNz);
    transpose_kernel<<<dim3(Dz/32, FFNz/32), tb, 0, s1>>>(w2, w2t, FFNz, Dz);
    cudaEventRecord(evW, s1);

    // stream 0: LN of ALL rows (x -> y/y16, kv -> kvn16), no weight dependency
    ln_dual_kernel<<<2 * MROWS, 256>>>(x, kv, y, y16, kvn16, MROWS, ln1_g, ln1_b);
    cudaEventRecord(evLN, 0);

    // half pipelines: half 0 on stream 0 (waits weights), half 1 on s1 (waits LN)
    cudaStreamWaitEvent(0, evW, 0);
    cudaStreamWaitEvent(s1, evLN, 0);

    for (int hh = 0; hh < 2; hh++) {
        cudaStream_t st = (hh == 0) ? (cudaStream_t)0 : s1;
        size_t R  = (size_t)hh * HROWS;
        const float* xh  = x  + R * Dz;
        const int*   mh  = mask + (size_t)hh * 2 * S2z;

        float*  yh    = y     + R * Dz;
        float*  x2h   = x2    + R * Dz;
        __half* y16h  = y16   + R * Dz;
        __half* kvnh  = kvn16 + R * Dz;
        __half* q16h  = q16   + R * Dz;
        __half* kv16h = kv16  + R * 4096;
        __half* o16h  = o16   + R * Dz;
        __half* yf16h = yf16  + R * Dz;
        __half* h16h  = h16   + R * FFNz;
        float*  outh  = out   + R * Dz;

        // KV mega-GEMM (both layers' K,V for this half)
        hgemm<<<gKVH, 256, GEMM_SMEM, st>>>(Dz, kvnh, Dz, kvwt, Dz,
            nullptr, kv16h, 4096, nullptr, nullptr, 0, 0);

        for (int l = 0; l < 2; l++) {
            hgemm<<<gProjH, 256, GEMM_SMEM, st>>>(Dz, y16h, Dz, qwt[l], Dz,
                nullptr, q16h, Dz, nullptr, nullptr, 0, 0);

            flash16_kernel<<<gFlashH, 256, FLASH_SMEM, st>>>(
                q16h, kv16h + l*2048, kv16h + l*2048 + 1024, 4096, mh, o16h);

            hgemm<<<gProjH, 256, GEMM_SMEM, st>>>(Dz, o16h, Dz, owt[l], Dz,
                yh, y16h, Dz, ob[l], yh, Dz, 0);
        }

        // x2 = x + y ; yf16 = LN(x2)
        ln_add_kernel<<<HROWS, 256, 0, st>>>(yh, xh, x2h, yf16h, ln2_g, ln2_b);

        // FFN
        hgemm<<<gF1H, 256, GEMM_SMEM, st>>>(Dz, yf16h, Dz, w1t, Dz,
            nullptr, h16h, FFNz, b1, nullptr, 0, 1);
        hgemm<<<gProjH, 256, GEMM_SMEM, st>>>(FFNz, h16h, FFNz, w2t, FFNz,
            outh, nullptr, Dz, b2, x2h, Dz, 0);
    }

    // join
    cudaEventRecord(evEnd, s1);
    cudaStreamWaitEvent(0, evEnd, 0);
}

// round 14
// speedup vs baseline: 1.1721x; 1.1721x over previous
#include <cuda_runtime.h>
#include <cuda_fp16.h>
#include <cstdint>
#include <math.h>

// Problem constants
#define Bz   4
#define S1z  1024
#define S2z  1024
#define Dz   1024
#define Hz   16
#define DKz  64
#define FFNz 4096

#define MROWS (Bz * S1z)        // 4096
#define HROWS (MROWS / 2)       // 2048 rows per half (2 batches)

// ---------------- scratch ----------------
__device__ float  g_y   [Bz * S1z * Dz];
__device__ float  g_x2  [Bz * S1z * Dz];
__device__ __half g_y16  [Bz * S1z * Dz];
__device__ __half g_kvn16[Bz * S2z * Dz];            // compacted per batch
__device__ __half g_q16  [Bz * S1z * Dz];
__device__ __half g_kv16 [(size_t)Bz * S2z * 4096];  // compacted K/V, ld=4096
__device__ __half g_o16  [Bz * S1z * Dz];
__device__ __half g_yf16 [Bz * S1z * Dz];
__device__ __half g_h16  [(size_t)Bz * S1z * FFNz];
__device__ __half g_wth  [16 * 1024 * 1024];
__device__ int    g_rank [Bz * S2z];                 // exclusive scan of mask
__device__ int    g_nv   [Bz];                       // valid count per batch

// ---------------- helpers ----------------
__device__ __forceinline__ uint32_t smem_u32(const void* p) {
    return (uint32_t)__cvta_generic_to_shared(p);
}
__device__ __forceinline__ void cp16(uint32_t dst, const void* src) {
    asm volatile("cp.async.cg.shared.global [%0], [%1], 16;" :: "r"(dst), "l"(src));
}
__device__ __forceinline__ void mma_f16(float* c, const uint32_t* a, const uint32_t* b) {
    asm volatile("mma.sync.aligned.m16n8k16.row.col.f32.f16.f16.f32 "
                 "{%0,%1,%2,%3},{%4,%5,%6,%7},{%8,%9},{%0,%1,%2,%3};"
                 : "+f"(c[0]), "+f"(c[1]), "+f"(c[2]), "+f"(c[3])
                 : "r"(a[0]), "r"(a[1]), "r"(a[2]), "r"(a[3]), "r"(b[0]), "r"(b[1]));
}
__device__ __forceinline__ void ldsm4(uint32_t* r, uint32_t addr) {
    asm volatile("ldmatrix.sync.aligned.m8n8.x4.shared.b16 {%0,%1,%2,%3}, [%4];"
                 : "=r"(r[0]), "=r"(r[1]), "=r"(r[2]), "=r"(r[3]) : "r"(addr));
}
__device__ __forceinline__ void ldsm4t(uint32_t* r, uint32_t addr) {
    asm volatile("ldmatrix.sync.aligned.m8n8.x4.trans.shared.b16 {%0,%1,%2,%3}, [%4];"
                 : "=r"(r[0]), "=r"(r[1]), "=r"(r[2]), "=r"(r[3]) : "r"(addr));
}
__device__ __forceinline__ uint32_t h2pack(float a, float b) {
    __half2 h = __floats2half2_rn(a, b);
    return *(uint32_t*)&h;
}

// ---------------- mask prefix scan (one block per batch) ---------------------
__global__ void mask_scan_kernel(const int* __restrict__ mask,
                                 int* __restrict__ rank, int* __restrict__ nv)
{
    int b = blockIdx.x, tid = threadIdx.x;            // 1024 threads
    int m = mask[(size_t)b * S2z + tid] ? 1 : 0;
    int v = m;
    int lane = tid & 31, wid = tid >> 5;
    #pragma unroll
    for (int o = 1; o < 32; o <<= 1) {
        int t = __shfl_up_sync(0xffffffffu, v, o);
        if (lane >= o) v += t;
    }
    __shared__ int ws[32];
    if (lane == 31) ws[wid] = v;
    __syncthreads();
    if (wid == 0) {
        int w = ws[lane];
        #pragma unroll
        for (int o = 1; o < 32; o <<= 1) {
            int t = __shfl_up_sync(0xffffffffu, w, o);
            if (lane >= o) w += t;
        }
        ws[lane] = w;
    }
    __syncthreads();
    int incl = v + (wid ? ws[wid - 1] : 0);
    rank[(size_t)b * S2z + tid] = incl - m;           // exclusive rank
    if (tid == S2z - 1) nv[b] = incl;
}

// ---------------- fp16 tensor-core GEMM (optional per-batch row early-exit) --
#define HSTR 40
#define HSTAGE (256 * HSTR * 2)
#define GEMM_SMEM (3 * HSTAGE)

__global__ void __launch_bounds__(256)
hgemm(int K,
      const __half* __restrict__ A, int lda,
      const __half* __restrict__ Bt, int ldb,
      float* __restrict__ C32, __half* __restrict__ C16, int ldc,
      const float* __restrict__ bias,
      const float* __restrict__ res, int ldres, int relu,
      const int* __restrict__ nvp, int rpb)
{
    extern __shared__ __align__(16) char smc[];
    int tid = threadIdx.x;
    int bm = blockIdx.y * 128, bn = blockIdx.x * 128;
    if (nvp) {                                        // skip fully-dead row blocks
        int bb = bm / rpb, lr = bm % rpb;
        if (lr >= nvp[bb]) return;
    }
    int warp = tid >> 5, lane = tid & 31, g = lane >> 2, tg = lane & 3;
    int wn = warp & 1, wm = warp >> 1;

    uint32_t sb = smem_u32(smc);
    const int NT = K / 32;

    auto issue = [&](int t) {
        uint32_t base = sb + (uint32_t)((t % 3) * HSTAGE);
        #pragma unroll
        for (int i = 0; i < 2; i++) {
            int e = tid + i * 256, r = e >> 2, c = (e & 3) * 8;
            cp16(base + (uint32_t)(r * HSTR + c) * 2u,
                 A + (size_t)(bm + r) * lda + t * 32 + c);
        }
        #pragma unroll
        for (int i = 0; i < 2; i++) {
            int e = tid + i * 256, r = e >> 2, c = (e & 3) * 8;
            cp16(base + (uint32_t)((128 + r) * HSTR + c) * 2u,
                 Bt + (size_t)(bn + r) * ldb + t * 32 + c);
        }
        asm volatile("cp.async.commit_group;");
    };

    int q = lane >> 3, rr = lane & 7;
    uint32_t a_off[2][2];
    #pragma unroll
    for (int mi = 0; mi < 2; mi++)
        #pragma unroll
        for (int ks = 0; ks < 2; ks++)
            a_off[mi][ks] = (uint32_t)(((wm*32 + mi*16 + (q&1)*8 + rr) * HSTR
                                        + ks*16 + (q>>1)*8) * 2);
    uint32_t b_off[4][2];
    #pragma unroll
    for (int jp = 0; jp < 4; jp++)
        #pragma unroll
        for (int ks = 0; ks < 2; ks++)
            b_off[jp][ks] = (uint32_t)(((128 + wn*64 + jp*16 + (q>>1)*8 + rr) * HSTR
                                        + ks*16 + (q&1)*8) * 2);

    float acc[2][8][4] = {};

    issue(0);
    if (NT > 1) issue(1);

    for (int t = 0; t < NT; t++) {
        if (t + 1 < NT) asm volatile("cp.async.wait_group 1;");
        else            asm volatile("cp.async.wait_group 0;");
        __syncthreads();
        if (t + 2 < NT) issue(t + 2);

        uint32_t stage = sb + (uint32_t)((t % 3) * HSTAGE);
        #pragma unroll
        for (int ks = 0; ks < 2; ks++) {
            uint32_t a[2][4], b[4][4];
            #pragma unroll
            for (int mi = 0; mi < 2; mi++) ldsm4(a[mi], stage + a_off[mi][ks]);
            #pragma unroll
            for (int jp = 0; jp < 4; jp++) ldsm4(b[jp], stage + b_off[jp][ks]);
            #pragma unroll
            for (int mi = 0; mi < 2; mi++)
                #pragma unroll
                for (int jp = 0; jp < 4; jp++) {
                    mma_f16(acc[mi][jp*2],     a[mi], &b[jp][0]);
                    mma_f16(acc[mi][jp*2 + 1], a[mi], &b[jp][2]);
                }
        }
    }

    #pragma unroll
    for (int mi = 0; mi < 2; mi++) {
        #pragma unroll
        for (int j = 0; j < 8; j++) {
            int m0 = bm + wm*32 + mi*16 + g;
            int n0 = bn + wn*64 + j*8 + 2*tg;
            float v0 = acc[mi][j][0], v1 = acc[mi][j][1];
            float v2 = acc[mi][j][2], v3 = acc[mi][j][3];
            if (bias) {
                float b0 = bias[n0], b1 = bias[n0 + 1];
                v0 += b0; v1 += b1; v2 += b0; v3 += b1;
            }
            if (res) {
                v0 += res[(size_t)m0*ldres + n0];
                v1 += res[(size_t)m0*ldres + n0 + 1];
                v2 += res[(size_t)(m0 + 8)*ldres + n0];
                v3 += res[(size_t)(m0 + 8)*ldres + n0 + 1];
            }
            if (relu) {
                v0 = fmaxf(v0, 0.f); v1 = fmaxf(v1, 0.f);
                v2 = fmaxf(v2, 0.f); v3 = fmaxf(v3, 0.f);
            }
            if (C32) {
                *(float2*)&C32[(size_t)m0*ldc + n0]       = make_float2(v0, v1);
                *(float2*)&C32[(size_t)(m0 + 8)*ldc + n0] = make_float2(v2, v3);
            }
            if (C16) {
                *(__half2*)&C16[(size_t)m0*ldc + n0]       = __floats2half2_rn(v0, v1);
                *(__half2*)&C16[(size_t)(m0 + 8)*ldc + n0] = __floats2half2_rn(v2, v3);
            }
        }
    }
}

// ---------------- transpose + fp32->fp16 -------------------------------------
__global__ void transpose8_kernel(
    const float* s0, __half* d0, const float* s1, __half* d1,
    const float* s2, __half* d2, const float* s3, __half* d3,
    const float* s4, __half* d4, const float* s5, __half* d5,
    const float* s6, __half* d6, const float* s7, __half* d7)
{
    __shared__ float tile[32][33];
    const float* src; __half* dst;
    switch (blockIdx.z) {
        case 0: src = s0; dst = d0; break;
        case 1: src = s1; dst = d1; break;
        case 2: src = s2; dst = d2; break;
        case 3: src = s3; dst = d3; break;
        case 4: src = s4; dst = d4; break;
        case 5: src = s5; dst = d5; break;
        case 6: src = s6; dst = d6; break;
        default: src = s7; dst = d7; break;
    }
    int tx = threadIdx.x, ty = threadIdx.y;
    int c0 = blockIdx.x * 32, r0 = blockIdx.y * 32;
    #pragma unroll
    for (int j = 0; j < 32; j += 8)
        tile[ty + j][tx] = src[(size_t)(r0 + ty + j) * Dz + c0 + tx];
    __syncthreads();
    #pragma unroll
    for (int j = 0; j < 32; j += 8)
        dst[(size_t)(c0 + ty + j) * Dz + r0 + tx] = __float2half_rn(tile[tx][ty + j]);
}

__global__ void transpose_kernel(const float* __restrict__ src, __half* __restrict__ dst,
                                 int R, int C)
{
    __shared__ float tile[32][33];
    int tx = threadIdx.x, ty = threadIdx.y;
    int c0 = blockIdx.x * 32, r0 = blockIdx.y * 32;
    #pragma unroll
    for (int j = 0; j < 32; j += 8)
        tile[ty + j][tx] = src[(size_t)(r0 + ty + j) * C + c0 + tx];
    __syncthreads();
    #pragma unroll
    for (int j = 0; j < 32; j += 8)
        dst[(size_t)(c0 + ty + j) * R + r0 + tx] = __float2half_rn(tile[tx][ty + j]);
}

// ---------------- LayerNorm core ----------------------------------------------
__device__ __forceinline__ void ln_row(float4 v,
                                       float* out32, __half* out16, size_t row, int tid,
                                       const float* __restrict__ g,
                                       const float* __restrict__ bta)
{
    float s = v.x + v.y + v.z + v.w;
    float q = v.x*v.x + v.y*v.y + v.z*v.z + v.w*v.w;
    #pragma unroll
    for (int o = 16; o; o >>= 1) {
        s += __shfl_xor_sync(0xffffffffu, s, o);
        q += __shfl_xor_sync(0xffffffffu, q, o);
    }
    __shared__ float ss[8], qq[8];
    int lane = tid & 31, wid = tid >> 5;
    if (!lane) { ss[wid] = s; qq[wid] = q; }
    __syncthreads();
    if (tid < 32) {
        s = (tid < 8) ? ss[tid] : 0.f;
        q = (tid < 8) ? qq[tid] : 0.f;
        #pragma unroll
        for (int o = 4; o; o >>= 1) {
            s += __shfl_xor_sync(0xffffffffu, s, o);
            q += __shfl_xor_sync(0xffffffffu, q, o);
        }
        if (!tid) { ss[0] = s; qq[0] = q; }
    }
    __syncthreads();
    float mean = ss[0] * (1.f / Dz);
    float var  = qq[0] * (1.f / Dz) - mean * mean;
    float inv  = rsqrtf(var + 1e-5f);
    float4 gv = ((const float4*)g)[tid];
    float4 bv = ((const float4*)bta)[tid];
    float4 o4;
    o4.x = (v.x - mean) * inv * gv.x + bv.x;
    o4.y = (v.y - mean) * inv * gv.y + bv.y;
    o4.z = (v.z - mean) * inv * gv.z + bv.z;
    o4.w = (v.w - mean) * inv * gv.w + bv.w;
    if (out32) ((float4*)(out32 + row * (size_t)Dz))[tid] = o4;
    if (out16) {
        __half2 h0 = __floats2half2_rn(o4.x, o4.y);
        __half2 h1 = __floats2half2_rn(o4.z, o4.w);
        uint2 u = make_uint2(*(uint32_t*)&h0, *(uint32_t*)&h1);
        ((uint2*)(out16 + row * (size_t)Dz))[tid] = u;
    }
}

// LN over n1 rows of x (-> y32,y16) and kv rows (-> compacted kvn16).
// kv row r (batch-local): valid -> position rank[r]; invalid -> zero row at
// position nv + (r - rank[r]).  All pointers pre-offset per half.
__global__ void ln_dual_kernel(const float* __restrict__ x, const float* __restrict__ kv,
                               float* __restrict__ y32, __half* __restrict__ y16,
                               __half* __restrict__ kvn16, int n1,
                               const int* __restrict__ mask, const int* __restrict__ rank,
                               const int* __restrict__ nvp,
                               const float* __restrict__ g, const float* __restrict__ bta)
{
    int tid = threadIdx.x;
    if ((int)blockIdx.x < n1) {
        size_t row = blockIdx.x;
        float4 v = ((const float4*)(x + row * (size_t)Dz))[tid];
        ln_row(v, y32, y16, row, tid, g, bta);
    } else {
        int row = blockIdx.x - n1;                    // local kv row within half
        int bb = row / S2z, r = row % S2z;
        int rk = rank[row];
        int valid = mask[row];
        int pos = valid ? rk : (nvp[bb] + (r - rk));
        size_t orow = (size_t)bb * S2z + pos;
        if (valid) {
            float4 v = ((const float4*)(kv + (size_t)row * Dz))[tid];
            ln_row(v, nullptr, kvn16, orow, tid, g, bta);
        } else {
            ((uint2*)(kvn16 + orow * (size_t)Dz))[tid] = make_uint2(0u, 0u);
        }
    }
}

__global__ void ln_add_kernel(const float* __restrict__ in, const float* __restrict__ add,
                              float* __restrict__ sum32, __half* __restrict__ out16,
                              const float* __restrict__ g, const float* __restrict__ bta)
{
    size_t row = blockIdx.x;
    int tid = threadIdx.x;
    float4 v = ((const float4*)(in + row * (size_t)Dz))[tid];
    float4 a4 = ((const float4*)(add + row * (size_t)Dz))[tid];
    v.x += a4.x; v.y += a4.y; v.z += a4.z; v.w += a4.w;
    ((float4*)(sum32 + row * (size_t)Dz))[tid] = v;
    ln_row(v, nullptr, out16, row, tid, g, bta);
}

// ---------------- fused fp16 flash attention over COMPACTED keys -------------
#define FSTR 72
#define FLASH_SMEM ((2*64*FSTR + 2*64*FSTR) * 2)
#define SCALE2 0.180336880f   // 0.125 * log2(e)

__global__ void __launch_bounds__(256)
flash16_kernel(const __half* __restrict__ Q, const __half* __restrict__ Kg,
               const __half* __restrict__ Vg, int ldkv,
               const int* __restrict__ nvp, __half* __restrict__ O16)
{
    extern __shared__ char smc[];
    __half* Ks = (__half*)smc;
    __half* Vs = Ks + 2*64*FSTR;

    int bh = blockIdx.y;
    int b = bh / Hz, h = bh % Hz;
    int q0 = blockIdx.x * 128;
    int tid = threadIdx.x, warp = tid >> 5, lane = tid & 31, g = lane >> 2, tg = lane & 3;
    int q2 = lane >> 3, rr = lane & 7;

    const int nv = nvp[b];
    const int NT = (nv + 63) >> 6;

    const __half* Qb = Q  + ((size_t)(b*S1z + q0))*Dz + h*DKz;
    const __half* Kb = Kg + (size_t)b*S2z*ldkv + h*DKz;
    const __half* Vb = Vg + (size_t)b*S2z*ldkv + h*DKz;

    uint32_t qa[4][4];
    {
        int ml = warp*16 + g, mh = ml + 8;
        #pragma unroll
        for (int ki = 0; ki < 4; ki++) {
            qa[ki][0] = *(const uint32_t*)&Qb[(size_t)ml*Dz + ki*16 + tg*2];
            qa[ki][1] = *(const uint32_t*)&Qb[(size_t)mh*Dz + ki*16 + tg*2];
            qa[ki][2] = *(const uint32_t*)&Qb[(size_t)ml*Dz + ki*16 + 8 + tg*2];
            qa[ki][3] = *(const uint32_t*)&Qb[(size_t)mh*Dz + ki*16 + 8 + tg*2];
        }
    }

    uint32_t ksb = smem_u32(Ks), vsb = smem_u32(Vs);

    auto issue = [&](int t) {
        int buf = t & 1;
        #pragma unroll
        for (int i = 0; i < 2; i++) {
            int e = tid + i*256, r = e >> 3, c = (e & 7) * 8;
            cp16(ksb + (uint32_t)(buf*64*FSTR + r*FSTR + c)*2u,
                 Kb + (size_t)(t*64 + r)*ldkv + c);
        }
        #pragma unroll
        for (int i = 0; i < 2; i++) {
            int e = tid + i*256, r = e >> 3, c = (e & 7) * 8;
            cp16(vsb + (uint32_t)(buf*64*FSTR + r*FSTR + c)*2u,
                 Vb + (size_t)(t*64 + r)*ldkv + c);
        }
        asm volatile("cp.async.commit_group;");
    };

    uint32_t kb_off[4][4];
    #pragma unroll
    for (int jp = 0; jp < 4; jp++)
        #pragma unroll
        for (int ki = 0; ki < 4; ki++)
            kb_off[jp][ki] = (uint32_t)(((jp*16 + (q2>>1)*8 + rr) * FSTR
                                         + ki*16 + (q2&1)*8) * 2);
    uint32_t vb_off[4][4];
    #pragma unroll
    for (int ki = 0; ki < 4; ki++)
        #pragma unroll
        for (int jp = 0; jp < 4; jp++)
            vb_off[ki][jp] = (uint32_t)(((ki*16 + (q2&1)*8 + rr) * FSTR
                                         + jp*16 + (q2>>1)*8) * 2);

    float s_acc[8][4];
    float o_acc[8][4] = {};
    float m_lo = -INFINITY, m_hi = -INFINITY, l_lo = 0.f, l_hi = 0.f;
    int rl = warp*16 + g, rh = rl + 8;

    issue(0);
    for (int t = 0; t < NT; t++) {
        if (t + 1 < NT) { issue(t + 1); asm volatile("cp.async.wait_group 1;"); }
        else            { asm volatile("cp.async.wait_group 0;"); }
        __syncthreads();
        int buf = t & 1;
        uint32_t kbase = ksb + (uint32_t)(buf*64*FSTR)*2u;
        uint32_t vbase = vsb + (uint32_t)(buf*64*FSTR)*2u;

        #pragma unroll
        for (int j = 0; j < 8; j++)
            s_acc[j][0] = s_acc[j][1] = s_acc[j][2] = s_acc[j][3] = 0.f;
        #pragma unroll
        for (int ki = 0; ki < 4; ki++) {
            uint32_t bf[4][4];
            #pragma unroll
            for (int jp = 0; jp < 4; jp++) ldsm4(bf[jp], kbase + kb_off[jp][ki]);
            #pragma unroll
            for (int jp = 0; jp < 4; jp++) {
                mma_f16(s_acc[jp*2],     qa[ki], &bf[jp][0]);
                mma_f16(s_acc[jp*2 + 1], qa[ki], &bf[jp][2]);
            }
        }

        // tail-mask (col >= nv) + scale + online softmax (log2 domain)
        float rmax_lo = -INFINITY, rmax_hi = -INFINITY;
        #pragma unroll
        for (int j = 0; j < 8; j++) {
            int c0 = t*64 + j*8 + 2*tg;
            bool v0 = c0 < nv, v1 = c0 + 1 < nv;
            s_acc[j][0] = v0 ? s_acc[j][0]*SCALE2 : -1e9f;
            s_acc[j][1] = v1 ? s_acc[j][1]*SCALE2 : -1e9f;
            s_acc[j][2] = v0 ? s_acc[j][2]*SCALE2 : -1e9f;
            s_acc[j][3] = v1 ? s_acc[j][3]*SCALE2 : -1e9f;
            rmax_lo = fmaxf(rmax_lo, fmaxf(s_acc[j][0], s_acc[j][1]));
            rmax_hi = fmaxf(rmax_hi, fmaxf(s_acc[j][2], s_acc[j][3]));
        }
        rmax_lo = fmaxf(rmax_lo, __shfl_xor_sync(0xffffffffu, rmax_lo, 1));
        rmax_lo = fmaxf(rmax_lo, __shfl_xor_sync(0xffffffffu, rmax_lo, 2));
        rmax_hi = fmaxf(rmax_hi, __shfl_xor_sync(0xffffffffu, rmax_hi, 1));
        rmax_hi = fmaxf(rmax_hi, __shfl_xor_sync(0xffffffffu, rmax_hi, 2));
        float mn_lo = fmaxf(m_lo, rmax_lo), mn_hi = fmaxf(m_hi, rmax_hi);
        float al_lo = exp2f(m_lo - mn_lo), al_hi = exp2f(m_hi - mn_hi);
        m_lo = mn_lo; m_hi = mn_hi;

        float sum_lo = 0.f, sum_hi = 0.f;
        #pragma unroll
        for (int j = 0; j < 8; j++) {
            s_acc[j][0] = exp2f(s_acc[j][0] - mn_lo);
            s_acc[j][1] = exp2f(s_acc[j][1] - mn_lo);
            s_acc[j][2] = exp2f(s_acc[j][2] - mn_hi);
            s_acc[j][3] = exp2f(s_acc[j][3] - mn_hi);
            sum_lo += s_acc[j][0] + s_acc[j][1];
            sum_hi += s_acc[j][2] + s_acc[j][3];
        }
        sum_lo += __shfl_xor_sync(0xffffffffu, sum_lo, 1);
        sum_lo += __shfl_xor_sync(0xffffffffu, sum_lo, 2);
        sum_hi += __shfl_xor_sync(0xffffffffu, sum_hi, 1);
        sum_hi += __shfl_xor_sync(0xffffffffu, sum_hi, 2);
        l_lo = al_lo*l_lo + sum_lo;
        l_hi = al_hi*l_hi + sum_hi;
        #pragma unroll
        for (int j = 0; j < 8; j++) {
            o_acc[j][0] *= al_lo; o_acc[j][1] *= al_lo;
            o_acc[j][2] *= al_hi; o_acc[j][3] *= al_hi;
        }

        #pragma unroll
        for (int ki = 0; ki < 4; ki++) {
            uint32_t pa[4];
            pa[0] = h2pack(s_acc[2*ki    ][0], s_acc[2*ki    ][1]);
            pa[1] = h2pack(s_acc[2*ki    ][2], s_acc[2*ki    ][3]);
            pa[2] = h2pack(s_acc[2*ki + 1][0], s_acc[2*ki + 1][1]);
            pa[3] = h2pack(s_acc[2*ki + 1][2], s_acc[2*ki + 1][3]);
            #pragma unroll
            for (int jp = 0; jp < 4; jp++) {
                uint32_t vb[4];
                ldsm4t(vb, vbase + vb_off[ki][jp]);
                mma_f16(o_acc[jp*2],     pa, &vb[0]);
                mma_f16(o_acc[jp*2 + 1], pa, &vb[2]);
            }
        }
        __syncthreads();
    }

    float il_lo = 1.f / l_lo, il_hi = 1.f / l_hi;
    __half* Ob = O16 + ((size_t)(b*S1z + q0))*Dz + h*DKz;
    #pragma unroll
    for (int j = 0; j < 8; j++) {
        int c = j*8 + 2*tg;
        *(__half2*)&Ob[(size_t)rl*Dz + c] =
            __floats2half2_rn(o_acc[j][0]*il_lo, o_acc[j][1]*il_lo);
        *(__half2*)&Ob[(size_t)rh*Dz + c] =
            __floats2half2_rn(o_acc[j][2]*il_hi, o_acc[j][3]*il_hi);
    }
}

// ---------------- host orchestration ----------------
extern "C" void kernel_launch(void* const* d_in, const int* in_sizes, int n_in,
                              void* d_out, int out_size)
{
    const float* x     = (const float*)d_in[0];
    const float* kv    = (const float*)d_in[1];
    const int*   mask  = (const int*)  d_in[2];
    const float* ln1_g = (const float*)d_in[3];
    const float* ln1_b = (const float*)d_in[4];
    const float* qw[2] = { (const float*)d_in[5],  (const float*)d_in[10] };
    const float* kw[2] = { (const float*)d_in[6],  (const float*)d_in[11] };
    const float* vw[2] = { (const float*)d_in[7],  (const float*)d_in[12] };
    const float* ow[2] = { (const float*)d_in[8],  (const float*)d_in[13] };
    const float* ob[2] = { (const float*)d_in[9],  (const float*)d_in[14] };
    const float* ln2_g = (const float*)d_in[15];
    const float* ln2_b = (const float*)d_in[16];
    const float* w1    = (const float*)d_in[17];
    const float* b1    = (const float*)d_in[18];
    const float* w2    = (const float*)d_in[19];
    const float* b2    = (const float*)d_in[20];
    float* out = (float*)d_out;

    float *y, *x2;
    __half *y16, *kvn16, *q16, *kv16, *o16, *yf16, *h16, *wth;
    int *rank, *nv;
    cudaGetSymbolAddress((void**)&y,     g_y);
    cudaGetSymbolAddress((void**)&x2,    g_x2);
    cudaGetSymbolAddress((void**)&y16,   g_y16);
    cudaGetSymbolAddress((void**)&kvn16, g_kvn16);
    cudaGetSymbolAddress((void**)&q16,   g_q16);
    cudaGetSymbolAddress((void**)&kv16,  g_kv16);
    cudaGetSymbolAddress((void**)&o16,   g_o16);
    cudaGetSymbolAddress((void**)&yf16,  g_yf16);
    cudaGetSymbolAddress((void**)&h16,   g_h16);
    cudaGetSymbolAddress((void**)&wth,   g_wth);
    cudaGetSymbolAddress((void**)&rank,  g_rank);
    cudaGetSymbolAddress((void**)&nv,    g_nv);

    cudaFuncSetAttribute(flash16_kernel,
        cudaFuncAttributeMaxDynamicSharedMemorySize, FLASH_SMEM);
    cudaFuncSetAttribute(hgemm,
        cudaFuncAttributeMaxDynamicSharedMemorySize, GEMM_SMEM);

    // one-time side stream + events (same footprint class as R11 — passed)
    static cudaStream_t s1 = nullptr;
    static cudaEvent_t evFork = nullptr, evW = nullptr, evEnd = nullptr;
    if (!s1) {
        cudaStreamCreateWithFlags(&s1, cudaStreamNonBlocking);
        cudaEventCreateWithFlags(&evFork, cudaEventDisableTiming);
        cudaEventCreateWithFlags(&evW,    cudaEventDisableTiming);
        cudaEventCreateWithFlags(&evEnd,  cudaEventDisableTiming);
    }

    const size_t MM = 1024 * 1024;
    __half* qwt[2] = { wth + 0*MM, wth + 1*MM };
    __half* owt[2] = { wth + 2*MM, wth + 3*MM };
    __half* kvwt   = wth + 4*MM;
    __half* w1t    = wth + 8*MM;
    __half* w2t    = wth + 12*MM;

    dim3 tb(32, 8);
    dim3 gProjH(Dz/128, HROWS/128);     // (8, 16)
    dim3 gKVH(4096/128, HROWS/128);     // (32, 16) — CTAs self-prune via nv
    dim3 gFlashH(S1z/128, 2*Hz);        // (8, 32)
    dim3 gF1H(FFNz/128, HROWS/128);     // (32, 16)

    cudaEventRecord(evFork, 0);
    cudaStreamWaitEvent(s1, evFork, 0);

    // stream 0: mask scan (needed by both halves' LN) + transposes
    mask_scan_kernel<<<Bz, 1024>>>(mask, rank, nv);
    transpose8_kernel<<<dim3(32,32,8), tb>>>(
        qw[0], qwt[0], qw[1], qwt[1], ow[0], owt[0], ow[1], owt[1],
        kw[0], kvwt + 0*MM, vw[0], kvwt + 1*MM, kw[1], kvwt + 2*MM, vw[1], kvwt + 3*MM);
    transpose_kernel<<<dim3(FFNz/32, Dz/32), tb>>>(w1, w1t, Dz, FFNz);
    transpose_kernel<<<dim3(Dz/32, FFNz/32), tb>>>(w2, w2t, FFNz, Dz);
    cudaEventRecord(evW, 0);
    cudaStreamWaitEvent(s1, evW, 0);

    for (int hh = 0; hh < 2; hh++) {
        cudaStream_t st = (hh == 0) ? (cudaStream_t)0 : s1;
        size_t R  = (size_t)hh * HROWS;
        const float* xh  = x  + R * Dz;
        const float* kvh = kv + R * Dz;
        const int*   mh    = mask + (size_t)hh * 2 * S2z;
        const int*   rankh = rank + (size_t)hh * 2 * S2z;
        const int*   nvh   = nv + hh * 2;

        float*  yh    = y     + R * Dz;
        float*  x2h   = x2    + R * Dz;
        __half* y16h  = y16   + R * Dz;
        __half* kvnh  = kvn16 + R * Dz;
        __half* q16h  = q16   + R * Dz;
        __half* kv16h = kv16  + R * 4096;
        __half* o16h  = o16   + R * Dz;
        __half* yf16h = yf16  + R * Dz;
        __half* h16h  = h16   + R * FFNz;
        float*  outh  = out   + R * Dz;

        // LN of x-half; LN+compaction of kv-half
        ln_dual_kernel<<<2 * HROWS, 256, 0, st>>>(
            xh, kvh, yh, y16h, kvnh, HROWS, mh, rankh, nvh, ln1_g, ln1_b);

        // KV mega-GEMM over compacted rows only (early-exit beyond nv)
        hgemm<<<gKVH, 256, GEMM_SMEM, st>>>(Dz, kvnh, Dz, kvwt, Dz,
            nullptr, kv16h, 4096, nullptr, nullptr, 0, 0, nvh, S2z);

        for (int l = 0; l < 2; l++) {
            hgemm<<<gProjH, 256, GEMM_SMEM, st>>>(Dz, y16h, Dz, qwt[l], Dz,
                nullptr, q16h, Dz, nullptr, nullptr, 0, 0, nullptr, 0);

            flash16_kernel<<<gFlashH, 256, FLASH_SMEM, st>>>(
                q16h, kv16h + l*2048, kv16h + l*2048 + 1024, 4096, nvh, o16h);

            hgemm<<<gProjH, 256, GEMM_SMEM, st>>>(Dz, o16h, Dz, owt[l], Dz,
                yh, y16h, Dz, ob[l], yh, Dz, 0, nullptr, 0);
        }

        ln_add_kernel<<<HROWS, 256, 0, st>>>(yh, xh, x2h, yf16h, ln2_g, ln2_b);

        hgemm<<<gF1H, 256, GEMM_SMEM, st>>>(Dz, yf16h, Dz, w1t, Dz,
            nullptr, h16h, FFNz, b1, nullptr, 0, 1, nullptr, 0);
        hgemm<<<gProjH, 256, GEMM_SMEM, st>>>(FFNz, h16h, FFNz, w2t, FFNz,
            outh, nullptr, Dz, b2, x2h, Dz, 0, nullptr, 0);
    }

    cudaEventRecord(evEnd, s1);
    cudaStreamWaitEvent(0, evEnd, 0);
}